// round 1
// baseline (speedup 1.0000x reference)
#include <cuda_runtime.h>
#include <cuda_bf16.h>
#include <math.h>

// Problem constants
#define BATCH 4
#define SLEN 2048
#define DMODEL 1024
#define NHEADS 16
#define HDIM 64
#define QKV_LD 3072  // 3*DMODEL
#define MROWS (BATCH * SLEN)  // 8192

// Scratch (allocation-free rule: __device__ globals)
__device__ float g_qkv[(size_t)MROWS * QKV_LD];   // [8192, 3072]
__device__ float g_ctx[(size_t)MROWS * DMODEL];   // [8192, 1024]

// ---------------------------------------------------------------------------
// Tiled SGEMM: C[M,N] = A[M,K] @ B[K,N], row-major, M%128==0, N%128==0, K%8==0
// ---------------------------------------------------------------------------
__global__ __launch_bounds__(256) void sgemm_kernel(
    const float* __restrict__ A, const float* __restrict__ B,
    float* __restrict__ C, int M, int N, int K)
{
    const int BM = 128, BN = 128, BK = 8, TM = 8, TN = 8;
    __shared__ float As[BK][BM];
    __shared__ float Bs[BK][BN];

    const int tid = threadIdx.x;
    const int tx = tid & 15;        // 0..15 (column group)
    const int ty = tid >> 4;        // 0..15 (row group)

    const int brow = blockIdx.y;
    const int bcol = blockIdx.x;

    const float* Ablk = A + (size_t)brow * BM * K;
    const float* Bblk = B + (size_t)bcol * BN;

    // A tile load map: 128 rows x 8 cols = 256 float4
    const int a_row = tid >> 1;
    const int a_col = (tid & 1) << 2;
    // B tile load map: 8 rows x 128 cols = 256 float4
    const int b_row = tid >> 5;
    const int b_col = (tid & 31) << 2;

    float acc[TM][TN];
    #pragma unroll
    for (int i = 0; i < TM; i++)
        #pragma unroll
        for (int j = 0; j < TN; j++)
            acc[i][j] = 0.0f;

    for (int k0 = 0; k0 < K; k0 += BK) {
        float4 av = *(const float4*)&Ablk[(size_t)a_row * K + k0 + a_col];
        As[a_col + 0][a_row] = av.x;
        As[a_col + 1][a_row] = av.y;
        As[a_col + 2][a_row] = av.z;
        As[a_col + 3][a_row] = av.w;
        float4 bv = *(const float4*)&Bblk[(size_t)(k0 + b_row) * N + b_col];
        *(float4*)&Bs[b_row][b_col] = bv;
        __syncthreads();

        #pragma unroll
        for (int k = 0; k < BK; k++) {
            float a[TM], b[TN];
            #pragma unroll
            for (int i = 0; i < TM; i++) a[i] = As[k][ty * TM + i];
            #pragma unroll
            for (int j = 0; j < TN; j++) b[j] = Bs[k][tx * TN + j];
            #pragma unroll
            for (int i = 0; i < TM; i++)
                #pragma unroll
                for (int j = 0; j < TN; j++)
                    acc[i][j] += a[i] * b[j];
        }
        __syncthreads();
    }

    float* Cblk = C + (size_t)brow * BM * N + bcol * BN;
    #pragma unroll
    for (int i = 0; i < TM; i++) {
        #pragma unroll
        for (int j = 0; j < TN; j += 4) {
            float4 v = make_float4(acc[i][j], acc[i][j + 1], acc[i][j + 2], acc[i][j + 3]);
            *(float4*)&Cblk[(size_t)(ty * TM + i) * N + tx * TN + j] = v;
        }
    }
}

// ---------------------------------------------------------------------------
// Flash attention: one block per (b, h, 64-query tile). 256 threads = 8 warps,
// each warp owns 8 query rows. K tile = 32 keys per iteration, online softmax.
// qkv layout: row = (b*SLEN + s), col = t*1024 + h*64 + dd  (t=0:Q, 1:K, 2:V)
// ctx layout: row-major [8192, 1024], col = h*64 + dd
// ---------------------------------------------------------------------------
__global__ __launch_bounds__(256) void attn_kernel(
    const float* __restrict__ qkv, float* __restrict__ ctx)
{
    const int qt = blockIdx.x;   // query tile 0..31
    const int h  = blockIdx.y;   // head 0..15
    const int b  = blockIdx.z;   // batch 0..3

    const int tid  = threadIdx.x;
    const int w    = tid >> 5;   // warp 0..7
    const int lane = tid & 31;

    __shared__ float Qs[64][64];      // 16 KB
    __shared__ float Ks[32][68];      // 8.5 KB (pad 68: conflict-free float4 row reads)
    __shared__ float Vs[32][64];      // 8 KB
    __shared__ float Ps[8][8][32];    // 8 KB (per-warp P tile)

    const int q0 = qt * 64;
    const float* base  = qkv + (size_t)b * SLEN * QKV_LD + h * HDIM;
    const float* kbase = base + 1024;
    const float* vbase = base + 2048;

    // Load Q tile [64, 64] (1024 float4)
    for (int i = tid; i < 64 * 16; i += 256) {
        int row = i >> 4;
        int c4  = (i & 15) << 2;
        float4 v = *(const float4*)&base[(size_t)(q0 + row) * QKV_LD + c4];
        *(float4*)&Qs[row][c4] = v;
    }

    float m[8], l[8], acc0[8], acc1[8];
    #pragma unroll
    for (int r = 0; r < 8; r++) {
        m[r] = -1e30f; l[r] = 0.0f; acc0[r] = 0.0f; acc1[r] = 0.0f;
    }
    __syncthreads();

    for (int kt = 0; kt < SLEN; kt += 32) {
        // Cooperative load of K and V tiles [32, 64] (512 float4 each)
        for (int i = tid; i < 512; i += 256) {
            int row = i >> 4;
            int c4  = (i & 15) << 2;
            float4 kv = *(const float4*)&kbase[(size_t)(kt + row) * QKV_LD + c4];
            *(float4*)&Ks[row][c4] = kv;   // stride 68 floats = 272 B, 16B aligned
            float4 vv = *(const float4*)&vbase[(size_t)(kt + row) * QKV_LD + c4];
            *(float4*)&Vs[row][c4] = vv;
        }
        __syncthreads();

        // Scores: warp w rows [w*8, w*8+8), lane owns key j = lane
        float s[8];
        #pragma unroll
        for (int r = 0; r < 8; r++) s[r] = 0.0f;
        #pragma unroll
        for (int k4 = 0; k4 < 64; k4 += 4) {
            float4 kv = *(const float4*)&Ks[lane][k4];
            #pragma unroll
            for (int r = 0; r < 8; r++) {
                float4 q4 = *(const float4*)&Qs[w * 8 + r][k4];
                s[r] += q4.x * kv.x + q4.y * kv.y + q4.z * kv.z + q4.w * kv.w;
            }
        }

        // Online softmax update per row
        #pragma unroll
        for (int r = 0; r < 8; r++) {
            float sv = s[r] * 0.125f;   // 1/sqrt(64)
            float mx = sv;
            #pragma unroll
            for (int off = 16; off; off >>= 1)
                mx = fmaxf(mx, __shfl_xor_sync(0xffffffffu, mx, off));
            float mnew = fmaxf(m[r], mx);
            float p    = __expf(sv - mnew);
            float corr = __expf(m[r] - mnew);
            float ps = p;
            #pragma unroll
            for (int off = 16; off; off >>= 1)
                ps += __shfl_xor_sync(0xffffffffu, ps, off);
            l[r]    = l[r] * corr + ps;
            acc0[r] *= corr;
            acc1[r] *= corr;
            m[r]    = mnew;
            Ps[w][r][lane] = p;
        }
        __syncwarp();

        // PV accumulate: acc[r][c] += sum_j Ps[w][r][j] * Vs[j][lane + 32c]
        #pragma unroll
        for (int j4 = 0; j4 < 32; j4 += 4) {
            float v0[4], v1[4];
            #pragma unroll
            for (int jj = 0; jj < 4; jj++) {
                v0[jj] = Vs[j4 + jj][lane];
                v1[jj] = Vs[j4 + jj][lane + 32];
            }
            #pragma unroll
            for (int r = 0; r < 8; r++) {
                float4 p4 = *(const float4*)&Ps[w][r][j4];
                acc0[r] += p4.x * v0[0] + p4.y * v0[1] + p4.z * v0[2] + p4.w * v0[3];
                acc1[r] += p4.x * v1[0] + p4.y * v1[1] + p4.z * v1[2] + p4.w * v1[3];
            }
        }
        __syncthreads();
    }

    // Write ctx
    float* cbase = ctx + (size_t)b * SLEN * DMODEL + h * HDIM;
    #pragma unroll
    for (int r = 0; r < 8; r++) {
        float inv = 1.0f / l[r];
        int row = q0 + w * 8 + r;
        cbase[(size_t)row * DMODEL + lane]      = acc0[r] * inv;
        cbase[(size_t)row * DMODEL + lane + 32] = acc1[r] * inv;
    }
}

// ---------------------------------------------------------------------------
extern "C" void kernel_launch(void* const* d_in, const int* in_sizes, int n_in,
                              void* d_out, int out_size)
{
    const float* hs   = (const float*)d_in[0];  // [4, 2048, 1024]
    const float* wqkv = (const float*)d_in[1];  // [1024, 3072]
    const float* wout = (const float*)d_in[2];  // [1024, 1024]
    float* out = (float*)d_out;                 // [4, 2048, 1024]

    float* qkv = nullptr;
    float* ctx = nullptr;
    cudaGetSymbolAddress((void**)&qkv, g_qkv);
    cudaGetSymbolAddress((void**)&ctx, g_ctx);

    // 1) QKV projection: [8192, 1024] @ [1024, 3072] -> [8192, 3072]
    {
        dim3 grid(QKV_LD / 128, MROWS / 128);
        sgemm_kernel<<<grid, 256>>>(hs, wqkv, qkv, MROWS, QKV_LD, DMODEL);
    }

    // 2) Attention -> ctx [8192, 1024]
    {
        dim3 grid(SLEN / 64, NHEADS, BATCH);
        attn_kernel<<<grid, 256>>>(qkv, ctx);
    }

    // 3) Output projection: [8192, 1024] @ [1024, 1024] -> [8192, 1024]
    {
        dim3 grid(DMODEL / 128, MROWS / 128);
        sgemm_kernel<<<grid, 256>>>(ctx, wout, out, MROWS, DMODEL, DMODEL);
    }
}

// round 6
// speedup vs baseline: 4.9700x; 4.9700x over previous
#include <cuda_runtime.h>
#include <cuda_bf16.h>
#include <cstdint>
#include <math.h>

// Problem constants
#define BATCH 4
#define SLEN 2048
#define DMODEL 1024
#define NHEADS 16
#define HDIM 64
#define QKV_LD 3072
#define MROWS (BATCH * SLEN)  // 8192

// Scratch (allocation-free rule: __device__ globals)
__device__ float g_qkv[(size_t)MROWS * QKV_LD];       // [8192, 3072]
__device__ float g_ctx[(size_t)MROWS * DMODEL];       // [8192, 1024]
__device__ float g_wqkv_t[(size_t)QKV_LD * DMODEL];   // [3072, 1024]
__device__ float g_wout_t[(size_t)DMODEL * DMODEL];   // [1024, 1024]

// ---------------------------------------------------------------------------
// Helpers
// ---------------------------------------------------------------------------
__device__ __forceinline__ float tf32r(float x) {
    uint32_t u;
    asm("cvt.rna.tf32.f32 %0, %1;" : "=r"(u) : "f"(x));
    return __uint_as_float(u);
}

// m16n8k8 tf32 MMA: C[16x8] += A[16x8] * B[8x8]
__device__ __forceinline__ void mma8(float* c, const float* a, const float* b) {
    const uint32_t* A = reinterpret_cast<const uint32_t*>(a);
    const uint32_t* B = reinterpret_cast<const uint32_t*>(b);
    asm volatile(
        "mma.sync.aligned.m16n8k8.row.col.f32.tf32.tf32.f32 "
        "{%0,%1,%2,%3}, {%4,%5,%6,%7}, {%8,%9}, {%0,%1,%2,%3};"
        : "+f"(c[0]), "+f"(c[1]), "+f"(c[2]), "+f"(c[3])
        : "r"(A[0]), "r"(A[1]), "r"(A[2]), "r"(A[3]), "r"(B[0]), "r"(B[1]));
}

// Fast exp on the FMA pipe (avoids MUFU bottleneck). x <= ~1, result >= 0.
__device__ __forceinline__ float fexp(float x) {
    float t = fmaxf(x * 1.4426950408889634f, -120.0f);  // log2(e)
    float r = t + 12582912.0f;                          // round-to-int magic
    int   i = __float_as_int(r) - 0x4B400000;           // integer part
    float f = t - (r - 12582912.0f);                    // frac in [-0.5, 0.5]
    // 2^f, degree-5 Taylor in ln2 (max rel err ~2.4e-6 on [-0.5,0.5])
    float p = 0.0013333558f;
    p = fmaf(p, f, 0.0096181291f);
    p = fmaf(p, f, 0.0555041087f);
    p = fmaf(p, f, 0.2402265069f);
    p = fmaf(p, f, 0.6931471806f);
    p = fmaf(p, f, 1.0f);
    return __int_as_float(__float_as_int(p) + (i << 23));
}

// ---------------------------------------------------------------------------
// tf32 mma GEMM: C[M,N] = A[M,K] @ Bt[N,K]^T (both K-major).
// CTA tile 128x128, BK=32, 8 warps in 2x4, warp tile 64x32.
// ---------------------------------------------------------------------------
#define GSTR 40
__global__ __launch_bounds__(256) void mma_gemm_kernel(
    const float* __restrict__ A, const float* __restrict__ Bt,
    float* __restrict__ C, int M, int N, int K)
{
    __shared__ float As[128 * GSTR];
    __shared__ float Bs[128 * GSTR];

    const int tid = threadIdx.x;
    const int lane = tid & 31, wid = tid >> 5;
    const int g = lane >> 2, cq = lane & 3;
    const int wm = (wid >> 2) * 64, wn = (wid & 3) * 32;

    const float* Ablk = A + (size_t)blockIdx.y * 128 * K;
    const float* Bblk = Bt + (size_t)blockIdx.x * 128 * K;

    float acc[4][4][4] = {};

    for (int k0 = 0; k0 < K; k0 += 32) {
        #pragma unroll
        for (int i = 0; i < 4; i++) {
            int idx = tid + i * 256;         // 0..1023
            int row = idx >> 3;              // 0..127
            int c4 = (idx & 7) << 2;         // 0..28
            float4 av = *(const float4*)&Ablk[(size_t)row * K + k0 + c4];
            float4 bv = *(const float4*)&Bblk[(size_t)row * K + k0 + c4];
            float* pa = &As[row * GSTR + c4];
            pa[0] = tf32r(av.x); pa[1] = tf32r(av.y);
            pa[2] = tf32r(av.z); pa[3] = tf32r(av.w);
            float* pb = &Bs[row * GSTR + c4];
            pb[0] = tf32r(bv.x); pb[1] = tf32r(bv.y);
            pb[2] = tf32r(bv.z); pb[3] = tf32r(bv.w);
        }
        __syncthreads();

        #pragma unroll
        for (int ks = 0; ks < 4; ks++) {
            float a[4][4], b[4][2];
            #pragma unroll
            for (int mi = 0; mi < 4; mi++) {
                int r = wm + mi * 16 + g;
                a[mi][0] = As[r * GSTR + ks * 8 + cq];
                a[mi][1] = As[(r + 8) * GSTR + ks * 8 + cq];
                a[mi][2] = As[r * GSTR + ks * 8 + cq + 4];
                a[mi][3] = As[(r + 8) * GSTR + ks * 8 + cq + 4];
            }
            #pragma unroll
            for (int nf = 0; nf < 4; nf++) {
                int n = wn + nf * 8 + g;
                b[nf][0] = Bs[n * GSTR + ks * 8 + cq];
                b[nf][1] = Bs[n * GSTR + ks * 8 + cq + 4];
            }
            #pragma unroll
            for (int mi = 0; mi < 4; mi++)
                #pragma unroll
                for (int nf = 0; nf < 4; nf++)
                    mma8(acc[mi][nf], a[mi], b[nf]);
        }
        __syncthreads();
    }

    // Epilogue: c0,c1 -> (row, 2cq..2cq+1), c2,c3 -> (row+8, ...)
    #pragma unroll
    for (int mi = 0; mi < 4; mi++) {
        int row = blockIdx.y * 128 + wm + mi * 16 + g;
        #pragma unroll
        for (int nf = 0; nf < 4; nf++) {
            int col = blockIdx.x * 128 + wn + nf * 8 + 2 * cq;
            float2 v0 = make_float2(acc[mi][nf][0], acc[mi][nf][1]);
            float2 v1 = make_float2(acc[mi][nf][2], acc[mi][nf][3]);
            *(float2*)&C[(size_t)row * N + col] = v0;
            *(float2*)&C[(size_t)(row + 8) * N + col] = v1;
        }
    }
}

// ---------------------------------------------------------------------------
// Tiled transpose: out[c][r] = in[r][c], in is [R, C]
// ---------------------------------------------------------------------------
__global__ __launch_bounds__(256) void transpose_kernel(
    const float* __restrict__ in, float* __restrict__ out, int R, int C)
{
    __shared__ float t[32][33];
    int bx = blockIdx.x * 32, by = blockIdx.y * 32;
    int x = bx + threadIdx.x;
    #pragma unroll
    for (int i = 0; i < 32; i += 8) {
        int y = by + threadIdx.y + i;
        t[threadIdx.y + i][threadIdx.x] = in[(size_t)y * C + x];
    }
    __syncthreads();
    int xo = by + threadIdx.x;
    #pragma unroll
    for (int i = 0; i < 32; i += 8) {
        int yo = bx + threadIdx.y + i;
        out[(size_t)yo * R + xo] = t[threadIdx.x][threadIdx.y + i];
    }
}

// ---------------------------------------------------------------------------
// Flash attention with tensor-core mma. One CTA per (b, h, 64-query tile).
// 4 warps; warp w owns q rows [w*16, w*16+16). K-chunk = 32 keys.
// ---------------------------------------------------------------------------
#define QSTR 68   // Q/K smem stride (banks: 4g+c unique)
#define VSTR 72   // V smem stride   (banks: 8c+g unique)
#define PSTR 36   // P smem stride   (banks: 4g+c unique)
__global__ __launch_bounds__(128) void attn_mma_kernel(
    const float* __restrict__ qkv, float* __restrict__ ctx)
{
    __shared__ float Qs[64 * QSTR];      // 17408 B
    __shared__ float Ks[32 * QSTR];      //  8704 B
    __shared__ float Vs[32 * VSTR];      //  9216 B
    __shared__ float Ps[4][16 * PSTR];   //  9216 B

    const int qt = blockIdx.x, h = blockIdx.y, b = blockIdx.z;
    const int tid = threadIdx.x;
    const int lane = tid & 31, w = tid >> 5;
    const int g = lane >> 2, cq = lane & 3;

    const int q0 = qt * 64;
    const float* base = qkv + (size_t)b * SLEN * QKV_LD + h * HDIM;
    const float* kb = base + 1024;
    const float* vb = base + 2048;

    // Load Q tile [64,64], pre-scaled by 1/sqrt(64), tf32-rounded
    for (int i = tid; i < 1024; i += 128) {
        int row = i >> 4, c4 = (i & 15) << 2;
        float4 v = *(const float4*)&base[(size_t)(q0 + row) * QKV_LD + c4];
        float* p = &Qs[row * QSTR + c4];
        p[0] = tf32r(v.x * 0.125f); p[1] = tf32r(v.y * 0.125f);
        p[2] = tf32r(v.z * 0.125f); p[3] = tf32r(v.w * 0.125f);
    }

    float oacc[8][4] = {};
    float m0 = -1e30f, m8 = -1e30f, l0 = 0.0f, l8 = 0.0f;
    __syncthreads();

    for (int kt = 0; kt < SLEN; kt += 32) {
        // Load K, V tiles [32,64]
        for (int i = tid; i < 512; i += 128) {
            int row = i >> 4, c4 = (i & 15) << 2;
            float4 kv = *(const float4*)&kb[(size_t)(kt + row) * QKV_LD + c4];
            float* pk = &Ks[row * QSTR + c4];
            pk[0] = tf32r(kv.x); pk[1] = tf32r(kv.y);
            pk[2] = tf32r(kv.z); pk[3] = tf32r(kv.w);
            float4 vv = *(const float4*)&vb[(size_t)(kt + row) * QKV_LD + c4];
            float* pv = &Vs[row * VSTR + c4];
            pv[0] = tf32r(vv.x); pv[1] = tf32r(vv.y);
            pv[2] = tf32r(vv.z); pv[3] = tf32r(vv.w);
        }
        __syncthreads();

        // S = Q @ K^T  (16 rows x 32 keys per warp)
        float s[4][4] = {};
        const int r = w * 16 + g;
        #pragma unroll
        for (int ks = 0; ks < 8; ks++) {
            float a[4];
            a[0] = Qs[r * QSTR + ks * 8 + cq];
            a[1] = Qs[(r + 8) * QSTR + ks * 8 + cq];
            a[2] = Qs[r * QSTR + ks * 8 + cq + 4];
            a[3] = Qs[(r + 8) * QSTR + ks * 8 + cq + 4];
            #pragma unroll
            for (int nf = 0; nf < 4; nf++) {
                float bf[2];
                bf[0] = Ks[(nf * 8 + g) * QSTR + ks * 8 + cq];
                bf[1] = Ks[(nf * 8 + g) * QSTR + ks * 8 + cq + 4];
                mma8(s[nf], a, bf);
            }
        }

        // Online softmax. Rows: (r -> c0,c1), (r+8 -> c2,c3). Quad = lanes
        // sharing g, so xor 1/2 shuffles reduce across the row.
        float rmax0 = -1e30f, rmax8 = -1e30f;
        #pragma unroll
        for (int nf = 0; nf < 4; nf++) {
            rmax0 = fmaxf(rmax0, fmaxf(s[nf][0], s[nf][1]));
            rmax8 = fmaxf(rmax8, fmaxf(s[nf][2], s[nf][3]));
        }
        rmax0 = fmaxf(rmax0, __shfl_xor_sync(0xffffffffu, rmax0, 1));
        rmax0 = fmaxf(rmax0, __shfl_xor_sync(0xffffffffu, rmax0, 2));
        rmax8 = fmaxf(rmax8, __shfl_xor_sync(0xffffffffu, rmax8, 1));
        rmax8 = fmaxf(rmax8, __shfl_xor_sync(0xffffffffu, rmax8, 2));

        float mn0 = fmaxf(m0, rmax0), mn8 = fmaxf(m8, rmax8);
        float corr0 = fexp(m0 - mn0), corr8 = fexp(m8 - mn8);
        m0 = mn0; m8 = mn8;

        float sum0 = 0.0f, sum8 = 0.0f;
        #pragma unroll
        for (int nf = 0; nf < 4; nf++) {
            float p0 = fexp(s[nf][0] - mn0);
            float p1 = fexp(s[nf][1] - mn0);
            float p2 = fexp(s[nf][2] - mn8);
            float p3 = fexp(s[nf][3] - mn8);
            sum0 += p0 + p1;
            sum8 += p2 + p3;
            float* pp0 = &Ps[w][g * PSTR + nf * 8 + 2 * cq];
            pp0[0] = tf32r(p0); pp0[1] = tf32r(p1);
            float* pp8 = &Ps[w][(g + 8) * PSTR + nf * 8 + 2 * cq];
            pp8[0] = tf32r(p2); pp8[1] = tf32r(p3);
        }
        sum0 += __shfl_xor_sync(0xffffffffu, sum0, 1);
        sum0 += __shfl_xor_sync(0xffffffffu, sum0, 2);
        sum8 += __shfl_xor_sync(0xffffffffu, sum8, 1);
        sum8 += __shfl_xor_sync(0xffffffffu, sum8, 2);
        l0 = l0 * corr0 + sum0;
        l8 = l8 * corr8 + sum8;

        #pragma unroll
        for (int nf = 0; nf < 8; nf++) {
            oacc[nf][0] *= corr0; oacc[nf][1] *= corr0;
            oacc[nf][2] *= corr8; oacc[nf][3] *= corr8;
        }
        __syncwarp();

        // O += P @ V  (16 rows x 64 dims per warp)
        #pragma unroll
        for (int ks = 0; ks < 4; ks++) {
            float a[4];
            a[0] = Ps[w][g * PSTR + ks * 8 + cq];
            a[1] = Ps[w][(g + 8) * PSTR + ks * 8 + cq];
            a[2] = Ps[w][g * PSTR + ks * 8 + cq + 4];
            a[3] = Ps[w][(g + 8) * PSTR + ks * 8 + cq + 4];
            #pragma unroll
            for (int nf = 0; nf < 8; nf++) {
                float bf[2];
                bf[0] = Vs[(ks * 8 + cq) * VSTR + nf * 8 + g];
                bf[1] = Vs[(ks * 8 + cq + 4) * VSTR + nf * 8 + g];
                mma8(oacc[nf], a, bf);
            }
        }
        __syncthreads();
    }

    // Normalize and store
    float inv0 = 1.0f / l0, inv8 = 1.0f / l8;
    float* cb = ctx + (size_t)b * SLEN * DMODEL + h * HDIM;
    int row0 = q0 + w * 16 + g;
    #pragma unroll
    for (int nf = 0; nf < 8; nf++) {
        int col = nf * 8 + 2 * cq;
        float2 v0 = make_float2(oacc[nf][0] * inv0, oacc[nf][1] * inv0);
        float2 v1 = make_float2(oacc[nf][2] * inv8, oacc[nf][3] * inv8);
        *(float2*)&cb[(size_t)row0 * DMODEL + col] = v0;
        *(float2*)&cb[(size_t)(row0 + 8) * DMODEL + col] = v1;
    }
}

// ---------------------------------------------------------------------------
extern "C" void kernel_launch(void* const* d_in, const int* in_sizes, int n_in,
                              void* d_out, int out_size)
{
    const float* hs   = (const float*)d_in[0];
    const float* wqkv = (const float*)d_in[1];
    const float* wout = (const float*)d_in[2];
    float* out = (float*)d_out;

    float *qkv, *ctx, *wqkv_t, *wout_t;
    cudaGetSymbolAddress((void**)&qkv, g_qkv);
    cudaGetSymbolAddress((void**)&ctx, g_ctx);
    cudaGetSymbolAddress((void**)&wqkv_t, g_wqkv_t);
    cudaGetSymbolAddress((void**)&wout_t, g_wout_t);

    // 0) Transpose weights to [N, K] K-major
    {
        dim3 blk(32, 8);
        transpose_kernel<<<dim3(QKV_LD / 32, DMODEL / 32), blk>>>(wqkv, wqkv_t, DMODEL, QKV_LD);
        transpose_kernel<<<dim3(DMODEL / 32, DMODEL / 32), blk>>>(wout, wout_t, DMODEL, DMODEL);
    }

    // 1) QKV projection (mma tf32): [8192,1024] @ [1024,3072]
    {
        dim3 grid(QKV_LD / 128, MROWS / 128);
        mma_gemm_kernel<<<grid, 256>>>(hs, wqkv_t, qkv, MROWS, QKV_LD, DMODEL);
    }

    // 2) Attention (mma tf32)
    {
        dim3 grid(SLEN / 64, NHEADS, BATCH);
        attn_mma_kernel<<<grid, 128>>>(qkv, ctx);
    }

    // 3) Output projection (mma tf32): [8192,1024] @ [1024,1024]
    {
        dim3 grid(DMODEL / 128, MROWS / 128);
        mma_gemm_kernel<<<grid, 256>>>(ctx, wout_t, out, MROWS, DMODEL, DMODEL);
    }
}